// round 1
// baseline (speedup 1.0000x reference)
#include <cuda_runtime.h>
#include <cuda_bf16.h>
#include <math.h>

#define NN 50000
#define NE 400000
#define D  128
#define H  8
#define DK 16

// ---------------- scratch (static device memory; no allocation allowed) ----
__device__ float g_Ku[NN*D], g_Qu[NN*D], g_Vou[NN*D], g_Vmu[NN*D];
__device__ float g_Ki[NN*D], g_Qi[NN*D], g_Voi[NN*D], g_Vmi[NN*D];
__device__ float g_raw[NE*H], g_E1[NE*H], g_E2[NE*H];
__device__ float g_m1[NN*H], g_m2[NN*H], g_z1[NN*H], g_z2[NN*H];
__device__ float g_lt_i[NN*D], g_ht_i[NN*D], g_lt_u[NN*D], g_ht_u[NN*D];
__device__ float g_hzl[NN*D], g_hzh[NN*D], g_xp[NN*D], g_t[NN*D];
__device__ float g_WkuE[D*D], g_WkiE[D*D], g_bkuE[D], g_bkiE[D];

// ---------------- helpers ---------------------------------------------------
__device__ __forceinline__ void atomicMaxF(float* addr, float v) {
    if (v >= 0.f) atomicMax((int*)addr, __float_as_int(v));
    else          atomicMin((unsigned int*)addr, __float_as_uint(v));
}

// ---------------- fused weight: Weff[k][h*16+j] = sum_i W[k][h*16+i]*ra[h][i][j]
__global__ void fuse_w(const float* __restrict__ W, const float* __restrict__ ra,
                       float* __restrict__ Weff) {
    int k = blockIdx.x;        // 0..127
    int j = threadIdx.x;       // 0..127
    int h = j >> 4, jj = j & 15;
    float s = 0.f;
    #pragma unroll
    for (int i = 0; i < 16; i++)
        s += W[k*D + h*16 + i] * ra[h*256 + i*16 + jj];
    Weff[k*D + j] = s;
}

__global__ void fuse_b(const float* __restrict__ b, const float* __restrict__ ra,
                       float* __restrict__ beff) {
    int j = threadIdx.x;
    int h = j >> 4, jj = j & 15;
    float s = 0.f;
    #pragma unroll
    for (int i = 0; i < 16; i++)
        s += b[h*16 + i] * ra[h*256 + i*16 + jj];
    beff[j] = s;
}

// ---------------- SGEMM: out[n,128] = epi(A[n,128] @ W[128,128] + bias) -----
// epi: 0 = none, 1 = tanh, 2 = skip blend: acc*alpha + aux*(1-alpha)
__global__ void __launch_bounds__(256)
gemm_epi(const float* __restrict__ A, const float* __restrict__ W,
         const float* __restrict__ bias, float* __restrict__ out, int n,
         int epi, const float* __restrict__ aux,
         const float* __restrict__ skipv, int skipidx)
{
    extern __shared__ float sm[];
    float* As = sm;             // 64 x 128
    float* Ws = sm + 64*D;      // 128 x 128
    int tid  = threadIdx.x;
    int row0 = blockIdx.x * 64;

    const float4* W4  = (const float4*)W;
    float4*       Ws4 = (float4*)Ws;
    #pragma unroll
    for (int i = 0; i < 16; i++) Ws4[tid + i*256] = W4[tid + i*256];

    const float4* A4  = (const float4*)A;
    float4*       As4 = (float4*)As;
    #pragma unroll
    for (int i = 0; i < 8; i++) {
        int idx = tid + i*256;           // float4 index within tile
        int r = idx >> 5;                // tile row
        float4 v = make_float4(0.f,0.f,0.f,0.f);
        if (row0 + r < n) v = A4[row0*32 + idx];
        As4[idx] = v;
    }
    __syncthreads();

    int tx = tid & 31;   // cols tx*4 .. tx*4+3
    int ty = tid >> 5;   // rows ty*8 .. ty*8+7

    float acc[8][4];
    #pragma unroll
    for (int i = 0; i < 8; i++) { acc[i][0]=acc[i][1]=acc[i][2]=acc[i][3]=0.f; }

    const float* Ab = As + (ty*8)*D;
    #pragma unroll 4
    for (int k = 0; k < D; k++) {
        float4 w = ((float4*)(Ws + k*D))[tx];
        #pragma unroll
        for (int i = 0; i < 8; i++) {
            float a = Ab[i*D + k];
            acc[i][0] += a*w.x; acc[i][1] += a*w.y;
            acc[i][2] += a*w.z; acc[i][3] += a*w.w;
        }
    }

    float4 b = ((const float4*)bias)[tx];
    float alpha = 0.f;
    if (epi == 2) alpha = 1.f / (1.f + expf(-skipv[skipidx]));

    #pragma unroll
    for (int i = 0; i < 8; i++) {
        int row = row0 + ty*8 + i;
        if (row >= n) continue;
        float4 o;
        o.x = acc[i][0] + b.x; o.y = acc[i][1] + b.y;
        o.z = acc[i][2] + b.z; o.w = acc[i][3] + b.w;
        if (epi == 1) {
            o.x = tanhf(o.x); o.y = tanhf(o.y); o.z = tanhf(o.z); o.w = tanhf(o.w);
        } else if (epi == 2) {
            float4 hv = ((const float4*)aux)[row*32 + tx];
            float om = 1.f - alpha;
            o.x = o.x*alpha + hv.x*om; o.y = o.y*alpha + hv.y*om;
            o.z = o.z*alpha + hv.z*om; o.w = o.w*alpha + hv.w*om;
        }
        ((float4*)out)[row*32 + tx] = o;
    }
}

// ---------------- per-head 16x16 transform: Vout[n,h,:] = Vin[n,h,:] @ rm[h]
__global__ void headtrans(const float* __restrict__ Vin, const float* __restrict__ rm,
                          float* __restrict__ Vout, int n)
{
    __shared__ float srm[H*DK*DK];
    for (int i = threadIdx.x; i < H*DK*DK; i += 128) srm[i] = rm[i];
    __syncthreads();
    int j = threadIdx.x;           // 0..127
    int h = j >> 4;
    int lane = j & 31;
    int base = lane & 16;          // shfl source group within warp
    int jj = j & 15;
    for (int node = blockIdx.x; node < n; node += gridDim.x) {
        float myv = Vin[node*D + j];   // element i = j&15 of head h
        float s = 0.f;
        #pragma unroll
        for (int i = 0; i < 16; i++) {
            float vi = __shfl_sync(0xffffffffu, myv, base + i, 32);
            s += vi * srm[h*256 + i*16 + jj];
        }
        Vout[node*D + j] = s;
    }
}

// ---------------- edge pass A: raw scores + segment max --------------------
__global__ void edge_raw(const float* __restrict__ Qd, const float* __restrict__ Ks,
                         const int* __restrict__ src, const int* __restrict__ dst,
                         const float* __restrict__ rel_pri,
                         float* __restrict__ raw, float* __restrict__ m1,
                         float* __restrict__ m2, int E)
{
    int gw = (blockIdx.x * blockDim.x + threadIdx.x) >> 5;  // warp id = edge
    int lane = threadIdx.x & 31;
    if (gw >= E) return;
    int s = src[gw], d = dst[gw];
    float4 q = ((const float4*)Qd)[d*32 + lane];
    float4 k = ((const float4*)Ks)[s*32 + lane];
    float dp = q.x*k.x + q.y*k.y + q.z*k.z + q.w*k.w;
    dp += __shfl_xor_sync(0xffffffffu, dp, 1);
    dp += __shfl_xor_sync(0xffffffffu, dp, 2);
    if ((lane & 3) == 0) {
        int h = lane >> 2;
        float r = dp * rel_pri[h] * 0.25f;   // / sqrt(16)
        raw[gw*H + h] = r;
        atomicMaxF(&m1[d*H + h], r);
        atomicMaxF(&m2[d*H + h], 1.f / (r + 1e-6f));
    }
}

// ---------------- edge pass B: exp + segment sum ---------------------------
__global__ void edge_exp(const float* __restrict__ raw, const int* __restrict__ dst,
                         const float* __restrict__ m1, const float* __restrict__ m2,
                         float* __restrict__ z1, float* __restrict__ z2,
                         float* __restrict__ E1, float* __restrict__ E2, int E)
{
    int t = blockIdx.x * blockDim.x + threadIdx.x;
    if (t >= E*H) return;
    int e = t >> 3, h = t & 7;
    int d = dst[e];
    float r = raw[t];
    float a = expf(r - m1[d*H + h]);
    E1[t] = a;
    atomicAdd(&z1[d*H + h], a);
    float s2 = 1.f / (r + 1e-6f);
    float b2 = expf(s2 - m2[d*H + h]);
    E2[t] = b2;
    atomicAdd(&z2[d*H + h], b2);
}

// ---------------- edge pass C: weighted message scatter --------------------
__global__ void edge_msg(const float* __restrict__ Vm, const int* __restrict__ src,
                         const int* __restrict__ dst,
                         const float* __restrict__ E1, const float* __restrict__ E2,
                         const float* __restrict__ z1, const float* __restrict__ z2,
                         float* __restrict__ lt, float* __restrict__ ht, int E)
{
    int gw = (blockIdx.x * blockDim.x + threadIdx.x) >> 5;  // warp = edge
    int lane = threadIdx.x & 31;
    if (gw >= E) return;
    int s = src[gw], d = dst[gw];
    int h = lane >> 2;
    float w1 = E1[gw*H + h] / z1[d*H + h];
    float w2 = E2[gw*H + h] / z2[d*H + h];
    float4 v = ((const float4*)Vm)[s*32 + lane];
    float* lp = lt + d*D + lane*4;
    atomicAdd(lp + 0, v.x*w1); atomicAdd(lp + 1, v.y*w1);
    atomicAdd(lp + 2, v.z*w1); atomicAdd(lp + 3, v.w*w1);
    float* hp = ht + d*D + lane*4;
    atomicAdd(hp + 0, v.x*w2); atomicAdd(hp + 1, v.y*w2);
    atomicAdd(hp + 2, v.z*w2); atomicAdd(hp + 3, v.w*w2);
}

// ---------------- lt = ori + lt_agg ; ht = ori - ht_agg (in place) ---------
__global__ void mk_ltht(const float* __restrict__ ori, float* __restrict__ ltagg,
                        float* __restrict__ htagg, int n4)
{
    int i = blockIdx.x * blockDim.x + threadIdx.x;
    if (i >= n4) return;
    float4 o = ((const float4*)ori)[i];
    float4 l = ((float4*)ltagg)[i];
    float4 h = ((float4*)htagg)[i];
    l.x = o.x + l.x; l.y = o.y + l.y; l.z = o.z + l.z; l.w = o.w + l.w;
    h.x = o.x - h.x; h.y = o.y - h.y; h.z = o.z - h.z; h.w = o.w - h.w;
    ((float4*)ltagg)[i] = l;
    ((float4*)htagg)[i] = h;
}

// ---------------- gating: sc = softmax([<hzl,xp>,<hzh,xp>]); t = lt*sc0+ht*sc1
__global__ void sc_t(const float* __restrict__ hzl, const float* __restrict__ hzh,
                     const float* __restrict__ xp, const float* __restrict__ lt,
                     const float* __restrict__ ht, float* __restrict__ t, int n)
{
    int gw = (blockIdx.x * blockDim.x + threadIdx.x) >> 5;  // warp = node
    int lane = threadIdx.x & 31;
    if (gw >= n) return;
    float4 a = ((const float4*)hzl)[gw*32 + lane];
    float4 b = ((const float4*)hzh)[gw*32 + lane];
    float4 x = ((const float4*)xp)[gw*32 + lane];
    float s0 = a.x*x.x + a.y*x.y + a.z*x.z + a.w*x.w;
    float s1 = b.x*x.x + b.y*x.y + b.z*x.z + b.w*x.w;
    #pragma unroll
    for (int off = 16; off > 0; off >>= 1) {
        s0 += __shfl_xor_sync(0xffffffffu, s0, off);
        s1 += __shfl_xor_sync(0xffffffffu, s1, off);
    }
    float m = fmaxf(s0, s1);
    float e0 = expf(s0 - m), e1 = expf(s1 - m);
    float inv = 1.f / (e0 + e1);
    float c0 = e0 * inv, c1 = e1 * inv;
    float4 l = ((const float4*)lt)[gw*32 + lane];
    float4 h = ((const float4*)ht)[gw*32 + lane];
    float4 o;
    o.x = l.x*c0 + h.x*c1; o.y = l.y*c0 + h.y*c1;
    o.z = l.z*c0 + h.z*c1; o.w = l.w*c0 + h.w*c1;
    ((float4*)t)[gw*32 + lane] = o;
}

// ---------------- host ------------------------------------------------------
static inline void launch_gemm(const float* A, const float* W, const float* b,
                               float* out, int n, int epi, const float* aux,
                               const float* skipv, int skipidx)
{
    gemm_epi<<<(n + 63) / 64, 256, 98304>>>(A, W, b, out, n, epi, aux, skipv, skipidx);
}

template <typename T>
static float* sym(T& s) { void* p = nullptr; cudaGetSymbolAddress(&p, s); return (float*)p; }

extern "C" void kernel_launch(void* const* d_in, const int* in_sizes, int n_in,
                              void* d_out, int out_size)
{
    const float* h_user = (const float*)d_in[0];
    const float* h_item = (const float*)d_in[1];
    const int* buys_src = (const int*)d_in[2];
    const int* buys_dst = (const int*)d_in[3];
    const int* rev_src  = (const int*)d_in[4];
    const int* rev_dst  = (const int*)d_in[5];
    const float *Wk_u=(const float*)d_in[6],  *bk_u=(const float*)d_in[7];
    const float *Wk_i=(const float*)d_in[8],  *bk_i=(const float*)d_in[9];
    const float *Wq_u=(const float*)d_in[10], *bq_u=(const float*)d_in[11];
    const float *Wq_i=(const float*)d_in[12], *bq_i=(const float*)d_in[13];
    const float *Wv_u=(const float*)d_in[14], *bv_u=(const float*)d_in[15];
    const float *Wv_i=(const float*)d_in[16], *bv_i=(const float*)d_in[17];
    const float *Wa_u=(const float*)d_in[18], *ba_u=(const float*)d_in[19];
    const float *Wa_i=(const float*)d_in[20], *ba_i=(const float*)d_in[21];
    const float *Wf  =(const float*)d_in[22], *bf  =(const float*)d_in[23];
    const float *Wx  =(const float*)d_in[24], *bx  =(const float*)d_in[25];
    const float *rel_pri=(const float*)d_in[26];
    const float *rel_att=(const float*)d_in[27];
    const float *rel_msg=(const float*)d_in[28];
    const float *skipv  =(const float*)d_in[29];

    float* out_u = (float*)d_out;
    float* out_i = out_u + (size_t)NN * D;

    float *Ku=sym(g_Ku), *Qu=sym(g_Qu), *Vou=sym(g_Vou), *Vmu=sym(g_Vmu);
    float *Ki=sym(g_Ki), *Qi=sym(g_Qi), *Voi=sym(g_Voi), *Vmi=sym(g_Vmi);
    float *raw=sym(g_raw), *E1=sym(g_E1), *E2=sym(g_E2);
    float *m1=sym(g_m1), *m2=sym(g_m2), *z1=sym(g_z1), *z2=sym(g_z2);
    float *lt_i=sym(g_lt_i), *ht_i=sym(g_ht_i), *lt_u=sym(g_lt_u), *ht_u=sym(g_ht_u);
    float *hzl=sym(g_hzl), *hzh=sym(g_hzh), *xp=sym(g_xp), *tb=sym(g_t);
    float *WkuE=sym(g_WkuE), *WkiE=sym(g_WkiE), *bkuE=sym(g_bkuE), *bkiE=sym(g_bkiE);

    cudaFuncSetAttribute(gemm_epi, cudaFuncAttributeMaxDynamicSharedMemorySize, 98304);

    // --- fold rel_att into K-projection weights ---
    fuse_w<<<D, D>>>(Wk_u, rel_att,        WkuE);
    fuse_w<<<D, D>>>(Wk_i, rel_att + 2048, WkiE);
    fuse_b<<<1, D>>>(bk_u, rel_att,        bkuE);
    fuse_b<<<1, D>>>(bk_i, rel_att + 2048, bkiE);

    // --- node projections ---
    launch_gemm(h_user, WkuE, bkuE, Ku,  NN, 0, 0, 0, 0);
    launch_gemm(h_user, Wq_u, bq_u, Qu,  NN, 0, 0, 0, 0);
    launch_gemm(h_user, Wv_u, bv_u, Vou, NN, 0, 0, 0, 0);
    launch_gemm(h_item, WkiE, bkiE, Ki,  NN, 0, 0, 0, 0);
    launch_gemm(h_item, Wq_i, bq_i, Qi,  NN, 0, 0, 0, 0);
    launch_gemm(h_item, Wv_i, bv_i, Voi, NN, 0, 0, 0, 0);
    headtrans<<<2048, 128>>>(Vou, rel_msg,        Vmu, NN);
    headtrans<<<2048, 128>>>(Voi, rel_msg + 2048, Vmi, NN);

    const int EB = (NE + 7) / 8;                // warp-per-edge blocks
    const int XB = (NE * H + 255) / 256;

    // --- relation 0: user -buys-> item (dst = item) ---
    cudaMemsetAsync(m1, 0xFF, NN*H*sizeof(float));
    cudaMemsetAsync(m2, 0xFF, NN*H*sizeof(float));
    cudaMemsetAsync(z1, 0,    NN*H*sizeof(float));
    cudaMemsetAsync(z2, 0,    NN*H*sizeof(float));
    cudaMemsetAsync(lt_i, 0, (size_t)NN*D*sizeof(float));
    cudaMemsetAsync(ht_i, 0, (size_t)NN*D*sizeof(float));
    edge_raw<<<EB, 256>>>(Qi, Ku, buys_src, buys_dst, rel_pri, raw, m1, m2, NE);
    edge_exp<<<XB, 256>>>(raw, buys_dst, m1, m2, z1, z2, E1, E2, NE);
    edge_msg<<<EB, 256>>>(Vmu, buys_src, buys_dst, E1, E2, z1, z2, lt_i, ht_i, NE);

    // --- relation 1: item -rev-> user (dst = user) ---
    cudaMemsetAsync(m1, 0xFF, NN*H*sizeof(float));
    cudaMemsetAsync(m2, 0xFF, NN*H*sizeof(float));
    cudaMemsetAsync(z1, 0,    NN*H*sizeof(float));
    cudaMemsetAsync(z2, 0,    NN*H*sizeof(float));
    cudaMemsetAsync(lt_u, 0, (size_t)NN*D*sizeof(float));
    cudaMemsetAsync(ht_u, 0, (size_t)NN*D*sizeof(float));
    edge_raw<<<EB, 256>>>(Qu, Ki, rev_src, rev_dst, rel_pri + H, raw, m1, m2, NE);
    edge_exp<<<XB, 256>>>(raw, rev_dst, m1, m2, z1, z2, E1, E2, NE);
    edge_msg<<<EB, 256>>>(Vmi, rev_src, rev_dst, E1, E2, z1, z2, lt_u, ht_u, NE);

    const int NB4 = (NN * 32 + 255) / 256;
    const int WB  = (NN * 32 + 255) / 256;

    // --- update users (agg from relation 1) ---
    mk_ltht<<<NB4, 256>>>(Vou, lt_u, ht_u, NN*32);
    launch_gemm(lt_u, Wf, bf, hzl, NN, 1, 0, 0, 0);
    launch_gemm(ht_u, Wf, bf, hzh, NN, 1, 0, 0, 0);
    launch_gemm(Vou,  Wx, bx, xp,  NN, 1, 0, 0, 0);
    sc_t<<<WB, 256>>>(hzl, hzh, xp, lt_u, ht_u, tb, NN);
    launch_gemm(tb, Wa_u, ba_u, out_u, NN, 2, h_user, skipv, 0);

    // --- update items (agg from relation 0) ---
    mk_ltht<<<NB4, 256>>>(Voi, lt_i, ht_i, NN*32);
    launch_gemm(lt_i, Wf, bf, hzl, NN, 1, 0, 0, 0);
    launch_gemm(ht_i, Wf, bf, hzh, NN, 1, 0, 0, 0);
    launch_gemm(Voi,  Wx, bx, xp,  NN, 1, 0, 0, 0);
    sc_t<<<WB, 256>>>(hzl, hzh, xp, lt_i, ht_i, tb, NN);
    launch_gemm(tb, Wa_i, ba_i, out_i, NN, 2, h_item, skipv, 1);
}

// round 2
// speedup vs baseline: 1.1655x; 1.1655x over previous
#include <cuda_runtime.h>
#include <cuda_bf16.h>
#include <math.h>

#define NN 50000
#define NE 400000
#define D  128
#define H  8
#define DK 16

// ---------------- scratch (static device memory) ---------------------------
__device__ float g_Ku[NN*D], g_Qu[NN*D], g_Vou[NN*D], g_Vmu[NN*D];
__device__ float g_Ki[NN*D], g_Qi[NN*D], g_Voi[NN*D], g_Vmi[NN*D];
__device__ float g_raw[NE*H];
__device__ float g_ltht_u[2*NN*D], g_ltht_i[2*NN*D];
__device__ float g_hz[2*NN*D], g_xp[NN*D], g_t[NN*D];
__device__ float g_WkuE[D*D], g_WkiE[D*D], g_bkuE[D], g_bkiE[D];
__device__ int   g_deg[NN], g_rowptr[NN+1], g_cursor[NN], g_eidx[NE];

// ---------------- fused weight: Weff[k][h*16+j] = sum_i W[k][h*16+i]*ra[h][i][j]
__global__ void fuse_w(const float* __restrict__ W, const float* __restrict__ ra,
                       float* __restrict__ Weff) {
    int k = blockIdx.x, j = threadIdx.x;
    int h = j >> 4, jj = j & 15;
    float s = 0.f;
    #pragma unroll
    for (int i = 0; i < 16; i++)
        s += W[k*D + h*16 + i] * ra[h*256 + i*16 + jj];
    Weff[k*D + j] = s;
}

__global__ void fuse_b(const float* __restrict__ b, const float* __restrict__ ra,
                       float* __restrict__ beff) {
    int j = threadIdx.x;
    int h = j >> 4, jj = j & 15;
    float s = 0.f;
    #pragma unroll
    for (int i = 0; i < 16; i++)
        s += b[h*16 + i] * ra[h*256 + i*16 + jj];
    beff[j] = s;
}

// ---------------- SGEMM: out[n,128] = epi(A[n,128] @ W[128,128] + bias) -----
// epi: 0 = none, 1 = tanh, 2 = skip blend
__global__ void __launch_bounds__(256)
gemm_epi(const float* __restrict__ A, const float* __restrict__ W,
         const float* __restrict__ bias, float* __restrict__ out, int n,
         int epi, const float* __restrict__ aux,
         const float* __restrict__ skipv, int skipidx)
{
    extern __shared__ float sm[];
    float* As = sm;             // 64 x 128
    float* Ws = sm + 64*D;      // 128 x 128
    int tid  = threadIdx.x;
    int row0 = blockIdx.x * 64;

    const float4* W4  = (const float4*)W;
    float4*       Ws4 = (float4*)Ws;
    #pragma unroll
    for (int i = 0; i < 16; i++) Ws4[tid + i*256] = W4[tid + i*256];

    const float4* A4  = (const float4*)A;
    float4*       As4 = (float4*)As;
    #pragma unroll
    for (int i = 0; i < 8; i++) {
        int idx = tid + i*256;
        int r = idx >> 5;
        float4 v = make_float4(0.f,0.f,0.f,0.f);
        if (row0 + r < n) v = A4[(size_t)row0*32 + idx];
        As4[idx] = v;
    }
    __syncthreads();

    int tx = tid & 31;   // cols tx*4..+3
    int ty = tid >> 5;   // rows ty*8..+7

    float acc[8][4];
    #pragma unroll
    for (int i = 0; i < 8; i++) { acc[i][0]=acc[i][1]=acc[i][2]=acc[i][3]=0.f; }

    const float* Ab = As + (ty*8)*D;
    #pragma unroll 4
    for (int k = 0; k < D; k++) {
        float4 w = ((float4*)(Ws + k*D))[tx];
        #pragma unroll
        for (int i = 0; i < 8; i++) {
            float a = Ab[i*D + k];
            acc[i][0] += a*w.x; acc[i][1] += a*w.y;
            acc[i][2] += a*w.z; acc[i][3] += a*w.w;
        }
    }

    float4 b = ((const float4*)bias)[tx];
    float alpha = 0.f;
    if (epi == 2) alpha = 1.f / (1.f + expf(-skipv[skipidx]));

    #pragma unroll
    for (int i = 0; i < 8; i++) {
        int row = row0 + ty*8 + i;
        if (row >= n) continue;
        float4 o;
        o.x = acc[i][0] + b.x; o.y = acc[i][1] + b.y;
        o.z = acc[i][2] + b.z; o.w = acc[i][3] + b.w;
        if (epi == 1) {
            o.x = tanhf(o.x); o.y = tanhf(o.y); o.z = tanhf(o.z); o.w = tanhf(o.w);
        } else if (epi == 2) {
            float4 hv = ((const float4*)aux)[(size_t)row*32 + tx];
            float om = 1.f - alpha;
            o.x = o.x*alpha + hv.x*om; o.y = o.y*alpha + hv.y*om;
            o.z = o.z*alpha + hv.z*om; o.w = o.w*alpha + hv.w*om;
        }
        ((float4*)out)[(size_t)row*32 + tx] = o;
    }
}

// ---------------- per-head 16x16 transform: Vout[n,h,:] = Vin[n,h,:] @ rm[h]
__global__ void headtrans(const float* __restrict__ Vin, const float* __restrict__ rm,
                          float* __restrict__ Vout, int n)
{
    __shared__ float srm[H*DK*DK];
    for (int i = threadIdx.x; i < H*DK*DK; i += 128) srm[i] = rm[i];
    __syncthreads();
    int j = threadIdx.x;
    int h = j >> 4;
    int base = (j & 31) & 16;
    int jj = j & 15;
    for (int node = blockIdx.x; node < n; node += gridDim.x) {
        float myv = Vin[node*D + j];
        float s = 0.f;
        #pragma unroll
        for (int i = 0; i < 16; i++) {
            float vi = __shfl_sync(0xffffffffu, myv, base + i, 32);
            s += vi * srm[h*256 + i*16 + jj];
        }
        Vout[node*D + j] = s;
    }
}

// ---------------- CSR build -------------------------------------------------
__global__ void hist_k(const int* __restrict__ dst, int* __restrict__ deg, int E) {
    int i = blockIdx.x * blockDim.x + threadIdx.x;
    if (i < E) atomicAdd(&deg[dst[i]], 1);
}

__global__ void scan_k(const int* __restrict__ deg, int* __restrict__ rowptr,
                       int* __restrict__ cursor, int n)
{
    __shared__ int sdata[1024];
    __shared__ int carry;
    int tid = threadIdx.x;
    if (tid == 0) carry = 0;
    __syncthreads();
    for (int base = 0; base < n; base += 1024) {
        int i = base + tid;
        int v = (i < n) ? deg[i] : 0;
        sdata[tid] = v;
        __syncthreads();
        #pragma unroll
        for (int off = 1; off < 1024; off <<= 1) {
            int t = (tid >= off) ? sdata[tid - off] : 0;
            __syncthreads();
            sdata[tid] += t;
            __syncthreads();
        }
        int excl = sdata[tid] - v + carry;
        if (i < n) { rowptr[i] = excl; cursor[i] = excl; }
        __syncthreads();
        if (tid == 0) carry += sdata[1023];
        __syncthreads();
    }
    if (tid == 0) rowptr[n] = carry;
}

__global__ void scatter_k(const int* __restrict__ dst, int* __restrict__ cursor,
                          int* __restrict__ eidx, int E)
{
    int i = blockIdx.x * blockDim.x + threadIdx.x;
    if (i < E) {
        int pos = atomicAdd(&cursor[dst[i]], 1);
        eidx[pos] = i;
    }
}

// ---------------- fused per-dst attention + aggregation --------------------
// warp per dst node: raw scores, dual softmax (lowf + highf), weighted V
// gather-sum, and lt = ori + agg_l, ht = ori - agg_h epilogue. No atomics.
__global__ void __launch_bounds__(256)
agg_k(const float* __restrict__ Q, const float* __restrict__ K,
      const float* __restrict__ Vm, const float* __restrict__ Vo,
      const int* __restrict__ src, const float* __restrict__ rel_pri,
      const int* __restrict__ rowptr, const int* __restrict__ eidx,
      float* __restrict__ raw, float* __restrict__ lt, float* __restrict__ ht,
      int n)
{
    int d = (blockIdx.x * blockDim.x + threadIdx.x) >> 5;
    int lane = threadIdx.x & 31;
    if (d >= n) return;
    int start = rowptr[d], end = rowptr[d+1];
    int h = lane >> 2;
    float pri = rel_pri[h] * 0.25f;   // 1/sqrt(16)

    float4 q = ((const float4*)Q)[(size_t)d*32 + lane];
    float m1 = -1e38f, m2 = -1e38f;

    // pass 1: raw scores + per-head maxes (stored in each lane; lanes within a
    // 4-group carry identical values for their head)
    for (int j = start; j < end; j++) {
        int e = eidx[j];
        int s = src[e];
        float4 k = ((const float4*)K)[(size_t)s*32 + lane];
        float dp = q.x*k.x + q.y*k.y + q.z*k.z + q.w*k.w;
        dp += __shfl_xor_sync(0xffffffffu, dp, 1);
        dp += __shfl_xor_sync(0xffffffffu, dp, 2);
        float r = dp * pri;
        if ((lane & 3) == 0) raw[e*8 + h] = r;
        m1 = fmaxf(m1, r);
        m2 = fmaxf(m2, 1.f / (r + 1e-6f));
    }
    __threadfence_block();   // make raw[] writes visible to all lanes

    // pass 2: partition sums
    float z1 = 0.f, z2 = 0.f;
    for (int j = start; j < end; j++) {
        int e = eidx[j];
        float r = raw[e*8 + h];
        z1 += expf(r - m1);
        z2 += expf(1.f / (r + 1e-6f) - m2);
    }
    float inv1 = (end > start) ? 1.f / z1 : 0.f;
    float inv2 = (end > start) ? 1.f / z2 : 0.f;

    // pass 3: weighted message gather-accumulate
    float4 al = make_float4(0.f,0.f,0.f,0.f);
    float4 ah = make_float4(0.f,0.f,0.f,0.f);
    for (int j = start; j < end; j++) {
        int e = eidx[j];
        int s = src[e];
        float r = raw[e*8 + h];
        float w1 = expf(r - m1) * inv1;
        float w2 = expf(1.f / (r + 1e-6f) - m2) * inv2;
        float4 v = ((const float4*)Vm)[(size_t)s*32 + lane];
        al.x += v.x*w1; al.y += v.y*w1; al.z += v.z*w1; al.w += v.w*w1;
        ah.x += v.x*w2; ah.y += v.y*w2; ah.z += v.z*w2; ah.w += v.w*w2;
    }

    // epilogue: lt = ori + agg_l ; ht = ori - agg_h
    float4 o = ((const float4*)Vo)[(size_t)d*32 + lane];
    float4 L = make_float4(o.x+al.x, o.y+al.y, o.z+al.z, o.w+al.w);
    float4 Hv = make_float4(o.x-ah.x, o.y-ah.y, o.z-ah.z, o.w-ah.w);
    ((float4*)lt)[(size_t)d*32 + lane] = L;
    ((float4*)ht)[(size_t)d*32 + lane] = Hv;
}

// ---------------- gating ----------------------------------------------------
__global__ void sc_t(const float* __restrict__ hzl, const float* __restrict__ hzh,
                     const float* __restrict__ xp, const float* __restrict__ lt,
                     const float* __restrict__ ht, float* __restrict__ t, int n)
{
    int gw = (blockIdx.x * blockDim.x + threadIdx.x) >> 5;
    int lane = threadIdx.x & 31;
    if (gw >= n) return;
    float4 a = ((const float4*)hzl)[(size_t)gw*32 + lane];
    float4 b = ((const float4*)hzh)[(size_t)gw*32 + lane];
    float4 x = ((const float4*)xp)[(size_t)gw*32 + lane];
    float s0 = a.x*x.x + a.y*x.y + a.z*x.z + a.w*x.w;
    float s1 = b.x*x.x + b.y*x.y + b.z*x.z + b.w*x.w;
    #pragma unroll
    for (int off = 16; off > 0; off >>= 1) {
        s0 += __shfl_xor_sync(0xffffffffu, s0, off);
        s1 += __shfl_xor_sync(0xffffffffu, s1, off);
    }
    float m = fmaxf(s0, s1);
    float e0 = expf(s0 - m), e1 = expf(s1 - m);
    float inv = 1.f / (e0 + e1);
    float c0 = e0 * inv, c1 = e1 * inv;
    float4 l = ((const float4*)lt)[(size_t)gw*32 + lane];
    float4 hv = ((const float4*)ht)[(size_t)gw*32 + lane];
    float4 o;
    o.x = l.x*c0 + hv.x*c1; o.y = l.y*c0 + hv.y*c1;
    o.z = l.z*c0 + hv.z*c1; o.w = l.w*c0 + hv.w*c1;
    ((float4*)t)[(size_t)gw*32 + lane] = o;
}

// ---------------- host ------------------------------------------------------
static inline void launch_gemm(const float* A, const float* W, const float* b,
                               float* out, int n, int epi, const float* aux,
                               const float* skipv, int skipidx)
{
    gemm_epi<<<(n + 63) / 64, 256, 98304>>>(A, W, b, out, n, epi, aux, skipv, skipidx);
}

template <typename T>
static void* symv(T& s) { void* p = nullptr; cudaGetSymbolAddress(&p, s); return p; }

extern "C" void kernel_launch(void* const* d_in, const int* in_sizes, int n_in,
                              void* d_out, int out_size)
{
    const float* h_user = (const float*)d_in[0];
    const float* h_item = (const float*)d_in[1];
    const int* buys_src = (const int*)d_in[2];
    const int* buys_dst = (const int*)d_in[3];
    const int* rev_src  = (const int*)d_in[4];
    const int* rev_dst  = (const int*)d_in[5];
    const float *Wk_u=(const float*)d_in[6],  *bk_u=(const float*)d_in[7];
    const float *Wk_i=(const float*)d_in[8],  *bk_i=(const float*)d_in[9];
    const float *Wq_u=(const float*)d_in[10], *bq_u=(const float*)d_in[11];
    const float *Wq_i=(const float*)d_in[12], *bq_i=(const float*)d_in[13];
    const float *Wv_u=(const float*)d_in[14], *bv_u=(const float*)d_in[15];
    const float *Wv_i=(const float*)d_in[16], *bv_i=(const float*)d_in[17];
    const float *Wa_u=(const float*)d_in[18], *ba_u=(const float*)d_in[19];
    const float *Wa_i=(const float*)d_in[20], *ba_i=(const float*)d_in[21];
    const float *Wf  =(const float*)d_in[22], *bf  =(const float*)d_in[23];
    const float *Wx  =(const float*)d_in[24], *bx  =(const float*)d_in[25];
    const float *rel_pri=(const float*)d_in[26];
    const float *rel_att=(const float*)d_in[27];
    const float *rel_msg=(const float*)d_in[28];
    const float *skipv  =(const float*)d_in[29];

    float* out_u = (float*)d_out;
    float* out_i = out_u + (size_t)NN * D;

    float *Ku=(float*)symv(g_Ku), *Qu=(float*)symv(g_Qu), *Vou=(float*)symv(g_Vou), *Vmu=(float*)symv(g_Vmu);
    float *Ki=(float*)symv(g_Ki), *Qi=(float*)symv(g_Qi), *Voi=(float*)symv(g_Voi), *Vmi=(float*)symv(g_Vmi);
    float *raw=(float*)symv(g_raw);
    float *ltht_u=(float*)symv(g_ltht_u), *ltht_i=(float*)symv(g_ltht_i);
    float *hz=(float*)symv(g_hz), *xp=(float*)symv(g_xp), *tb=(float*)symv(g_t);
    float *WkuE=(float*)symv(g_WkuE), *WkiE=(float*)symv(g_WkiE);
    float *bkuE=(float*)symv(g_bkuE), *bkiE=(float*)symv(g_bkiE);
    int *deg=(int*)symv(g_deg), *rowptr=(int*)symv(g_rowptr);
    int *cursor=(int*)symv(g_cursor), *eidx=(int*)symv(g_eidx);

    cudaFuncSetAttribute(gemm_epi, cudaFuncAttributeMaxDynamicSharedMemorySize, 98304);

    // --- fold rel_att into K-projection weights ---
    fuse_w<<<D, D>>>(Wk_u, rel_att,        WkuE);
    fuse_w<<<D, D>>>(Wk_i, rel_att + 2048, WkiE);
    fuse_b<<<1, D>>>(bk_u, rel_att,        bkuE);
    fuse_b<<<1, D>>>(bk_i, rel_att + 2048, bkiE);

    // --- node projections (launch #6 of the run = a gemm_epi, for ncu) ---
    launch_gemm(h_user, WkuE, bkuE, Ku,  NN, 0, 0, 0, 0);
    launch_gemm(h_user, Wq_u, bq_u, Qu,  NN, 0, 0, 0, 0);
    launch_gemm(h_user, Wv_u, bv_u, Vou, NN, 0, 0, 0, 0);
    launch_gemm(h_item, WkiE, bkiE, Ki,  NN, 0, 0, 0, 0);
    launch_gemm(h_item, Wq_i, bq_i, Qi,  NN, 0, 0, 0, 0);
    launch_gemm(h_item, Wv_i, bv_i, Voi, NN, 0, 0, 0, 0);
    headtrans<<<2048, 128>>>(Vou, rel_msg,        Vmu, NN);
    headtrans<<<2048, 128>>>(Voi, rel_msg + 2048, Vmi, NN);

    const int EB  = (NE + 255) / 256;
    const int AWB = (NN * 32 + 255) / 256;   // warp-per-dst blocks

    // --- relation 0: user -buys-> item (dst = item) ---
    cudaMemsetAsync(deg, 0, NN * sizeof(int));
    hist_k<<<EB, 256>>>(buys_dst, deg, NE);
    scan_k<<<1, 1024>>>(deg, rowptr, cursor, NN);
    scatter_k<<<EB, 256>>>(buys_dst, cursor, eidx, NE);
    agg_k<<<AWB, 256>>>(Qi, Ku, Vmu, Voi, buys_src, rel_pri,
                        rowptr, eidx, raw, ltht_i, ltht_i + (size_t)NN*D, NN);

    // --- relation 1: item -rev-> user (dst = user) ---
    cudaMemsetAsync(deg, 0, NN * sizeof(int));
    hist_k<<<EB, 256>>>(rev_dst, deg, NE);
    scan_k<<<1, 1024>>>(deg, rowptr, cursor, NN);
    scatter_k<<<EB, 256>>>(rev_dst, cursor, eidx, NE);
    agg_k<<<AWB, 256>>>(Qu, Ki, Vmi, Vou, rev_src, rel_pri + H,
                        rowptr, eidx, raw, ltht_u, ltht_u + (size_t)NN*D, NN);

    const int WB = (NN * 32 + 255) / 256;

    // --- update users (agg from relation 1) ---
    launch_gemm(ltht_u, Wf, bf, hz, 2*NN, 1, 0, 0, 0);   // hzl || hzh
    launch_gemm(Vou,    Wx, bx, xp,   NN, 1, 0, 0, 0);
    sc_t<<<WB, 256>>>(hz, hz + (size_t)NN*D, xp,
                      ltht_u, ltht_u + (size_t)NN*D, tb, NN);
    launch_gemm(tb, Wa_u, ba_u, out_u, NN, 2, h_user, skipv, 0);

    // --- update items (agg from relation 0) ---
    launch_gemm(ltht_i, Wf, bf, hz, 2*NN, 1, 0, 0, 0);
    launch_gemm(Voi,    Wx, bx, xp,   NN, 1, 0, 0, 0);
    sc_t<<<WB, 256>>>(hz, hz + (size_t)NN*D, xp,
                      ltht_i, ltht_i + (size_t)NN*D, tb, NN);
    launch_gemm(tb, Wa_i, ba_i, out_i, NN, 2, h_item, skipv, 1);
}